// round 1
// baseline (speedup 1.0000x reference)
#include <cuda_runtime.h>

#define NN   100000
#define NE   1600000
#define INC  128
#define OUTC 64

// Scratch (no cudaMalloc allowed)
__device__ float g_h[NN * OUTC];     // X @ W, 25.6 MB
__device__ float g_deg[NN];
__device__ float g_dis[NN];
__device__ int   g_is64;             // edge_index dtype flag

// ---------------------------------------------------------------------------
// Detect whether edge_index is int64 or int32 (JAX may demote int64->int32).
// If int64 (values < 100000), the high 32-bit word of each entry is 0.
// ---------------------------------------------------------------------------
__global__ void k_detect(const int* __restrict__ ei32) {
    if (threadIdx.x == 0 && blockIdx.x == 0) {
        // words 1,3,5 are high halves if int64; random indices if int32
        int hi0 = ei32[1], hi1 = ei32[3], hi2 = ei32[5];
        g_is64 = (hi0 == 0 && hi1 == 0 && hi2 == 0) ? 1 : 0;
    }
}

__device__ __forceinline__ int load_idx(const void* ei, int pos) {
    if (g_is64) return (int)((const long long*)ei)[pos];
    return ((const int*)ei)[pos];
}

// ---------------------------------------------------------------------------
// K0: out[i][c] = b[c]  (bias pre-loaded so scatter accumulates on top),
//     deg = 0
// ---------------------------------------------------------------------------
__global__ void k_init(float4* __restrict__ out4, const float4* __restrict__ b4) {
    int i = blockIdx.x * 256 + threadIdx.x;       // grid covers NN*16 exactly
    out4[i] = b4[i & 15];
    if (i < NN) g_deg[i] = 0.f;
}

// ---------------------------------------------------------------------------
// K1: deg[col] += w  (scalar float atomics, 1.6M ops, ~16-way avg contention)
// ---------------------------------------------------------------------------
__global__ void k_deg(const void* __restrict__ ei, const float* __restrict__ ew) {
    int e = blockIdx.x * 256 + threadIdx.x;
    if (e >= NE) return;
    int col = load_idx(ei, NE + e);
    atomicAdd(&g_deg[col], ew[e]);
}

// ---------------------------------------------------------------------------
// K2: dis = deg > 0 ? rsqrt(deg) : 0
// ---------------------------------------------------------------------------
__global__ void k_dis() {
    int i = blockIdx.x * 256 + threadIdx.x;
    if (i >= NN) return;
    float d = g_deg[i];
    g_dis[i] = d > 0.f ? rsqrtf(d) : 0.f;
}

// ---------------------------------------------------------------------------
// K3: h = X @ W.  W in shared (32KB, broadcast/multicast LDS).
// Block = 256 threads = 64 rows x 4 threads; each thread: 1 row x 16 cols.
// ---------------------------------------------------------------------------
__global__ void k_gemm(const float* __restrict__ x, const float* __restrict__ W) {
    __shared__ float4 Ws[INC * OUTC / 4];         // 2048 float4 = 32 KB
    int t = threadIdx.x;
    const float4* W4 = (const float4*)W;
    #pragma unroll
    for (int i = 0; i < 8; i++) Ws[t + 256 * i] = W4[t + 256 * i];
    __syncthreads();

    int r = blockIdx.x * 64 + (t >> 2);
    if (r >= NN) return;
    int cg = (t & 3) * 4;                         // float4-group base (cols 16*(t&3)..+15)

    float4 a0 = {0,0,0,0}, a1 = {0,0,0,0}, a2 = {0,0,0,0}, a3 = {0,0,0,0};
    const float4* xr = (const float4*)(x + (long long)r * INC);

    #pragma unroll 4
    for (int k4 = 0; k4 < 32; k4++) {
        float4 xv = __ldg(&xr[k4]);
        float xs[4] = {xv.x, xv.y, xv.z, xv.w};
        #pragma unroll
        for (int kk = 0; kk < 4; kk++) {
            int k = k4 * 4 + kk;
            float xk = xs[kk];
            float4 w0 = Ws[k * 16 + cg + 0];
            float4 w1 = Ws[k * 16 + cg + 1];
            float4 w2 = Ws[k * 16 + cg + 2];
            float4 w3 = Ws[k * 16 + cg + 3];
            a0.x += xk * w0.x; a0.y += xk * w0.y; a0.z += xk * w0.z; a0.w += xk * w0.w;
            a1.x += xk * w1.x; a1.y += xk * w1.y; a1.z += xk * w1.z; a1.w += xk * w1.w;
            a2.x += xk * w2.x; a2.y += xk * w2.y; a2.z += xk * w2.z; a2.w += xk * w2.w;
            a3.x += xk * w3.x; a3.y += xk * w3.y; a3.z += xk * w3.z; a3.w += xk * w3.w;
        }
    }
    float4* ho = (float4*)(g_h + (long long)r * OUTC);
    ho[(t & 3) * 4 + 0] = a0;
    ho[(t & 3) * 4 + 1] = a1;
    ho[(t & 3) * 4 + 2] = a2;
    ho[(t & 3) * 4 + 3] = a3;
}

// ---------------------------------------------------------------------------
// K4: scatter.  16 threads per edge, each handles one float4 (4 channels).
// Vectorized no-return reduction: red.global.add.v4.f32 (sm_90+).
// ---------------------------------------------------------------------------
__device__ __forceinline__ void red_add_v4(float4* addr, float4 v) {
    asm volatile("red.global.add.v4.f32 [%0], {%1,%2,%3,%4};"
                 :: "l"(addr), "f"(v.x), "f"(v.y), "f"(v.z), "f"(v.w)
                 : "memory");
}

__global__ void k_scatter(const void* __restrict__ ei, const float* __restrict__ ew,
                          float* __restrict__ out) {
    int tid = blockIdx.x * 256 + threadIdx.x;     // up to 25.6M < 2^31
    int e = tid >> 4;
    if (e >= NE) return;
    int j = tid & 15;
    int row = load_idx(ei, e);                    // broadcast within half-warp
    int col = load_idx(ei, NE + e);
    float norm = g_dis[row] * __ldg(&ew[e]) * g_dis[col];
    float4 v = ((const float4*)g_h)[row * 16 + j];
    float4 m = {norm * v.x, norm * v.y, norm * v.z, norm * v.w};
    red_add_v4(((float4*)out) + col * 16 + j, m);
}

// ---------------------------------------------------------------------------
// K5: sigmoid in-place
// ---------------------------------------------------------------------------
__global__ void k_sigmoid(float4* __restrict__ out4) {
    int i = blockIdx.x * 256 + threadIdx.x;       // grid covers NN*16 exactly
    float4 v = out4[i];
    v.x = 1.f / (1.f + __expf(-v.x));
    v.y = 1.f / (1.f + __expf(-v.y));
    v.z = 1.f / (1.f + __expf(-v.z));
    v.w = 1.f / (1.f + __expf(-v.w));
    out4[i] = v;
}

// ---------------------------------------------------------------------------
extern "C" void kernel_launch(void* const* d_in, const int* in_sizes, int n_in,
                              void* d_out, int out_size) {
    const float* x  = (const float*)d_in[0];
    const void*  ei = d_in[1];                    // int32 or int64, detected on-device
    const float* ew = (const float*)d_in[2];
    const float* W  = (const float*)d_in[3];
    const float* b  = (const float*)d_in[4];
    float* out = (float*)d_out;

    k_detect<<<1, 32>>>((const int*)ei);
    k_init<<<NN * 16 / 256, 256>>>((float4*)out, (const float4*)b);   // 6250 blocks
    k_deg<<<(NE + 255) / 256, 256>>>(ei, ew);
    k_dis<<<(NN + 255) / 256, 256>>>();
    k_gemm<<<(NN + 63) / 64, 256>>>(x, W);
    k_scatter<<<(NE * 16 + 255) / 256, 256>>>(ei, ew, out);
    k_sigmoid<<<NN * 16 / 256, 256>>>((float4*)out);
}

// round 6
// speedup vs baseline: 1.0016x; 1.0016x over previous
#include <cuda_runtime.h>

#define NN   100000
#define NE   1600000
#define INC  128
#define OUTC 64
#define NBLK 391                      // ceil(NN/256)

// ---- scratch (__device__ globals; no cudaMalloc allowed) -------------------
__device__ float              g_h[NN * OUTC];      // X @ W (25.6 MB)
__device__ float              g_deg[NN];
__device__ float              g_dis[NN];
__device__ int                g_cnt[NN];
__device__ int                g_bsum[NBLK];
__device__ int                g_bpre[NBLK];
__device__ int                g_off[NN + 1];
__device__ int                g_cur[NN];
__device__ unsigned long long g_rec[NE];           // packed {row:int32, norm:f32}
__device__ int                g_is64;

// ---------------------------------------------------------------------------
// dtype detection: int64 indices < 100000 have zero high words
// ---------------------------------------------------------------------------
__global__ void k_detect(const int* __restrict__ ei32) {
    if (threadIdx.x == 0) {
        int hi0 = ei32[1], hi1 = ei32[3], hi2 = ei32[5];
        g_is64 = (hi0 == 0 && hi1 == 0 && hi2 == 0) ? 1 : 0;
    }
}

__device__ __forceinline__ int load_idx(const void* ei, int pos) {
    if (g_is64) return (int)((const long long*)ei)[pos];
    return ((const int*)ei)[pos];
}

// ---------------------------------------------------------------------------
__global__ void k_zero() {
    int i = blockIdx.x * 256 + threadIdx.x;
    if (i < NN) { g_deg[i] = 0.f; g_cnt[i] = 0; }
}

// count[col]++, deg[col] += w
__global__ void k_count(const void* __restrict__ ei, const float* __restrict__ ew) {
    int e = blockIdx.x * 256 + threadIdx.x;
    if (e >= NE) return;
    int col = load_idx(ei, NE + e);
    atomicAdd(&g_cnt[col], 1);
    atomicAdd(&g_deg[col], ew[e]);
}

// per-block sums of cnt
__global__ void k_scan1() {
    __shared__ int s[256];
    int t = threadIdx.x;
    int i = blockIdx.x * 256 + t;
    s[t] = (i < NN) ? g_cnt[i] : 0;
    __syncthreads();
    #pragma unroll
    for (int st = 128; st > 0; st >>= 1) {
        if (t < st) s[t] += s[t + st];
        __syncthreads();
    }
    if (t == 0) g_bsum[blockIdx.x] = s[0];
}

// exclusive scan of the 391 block sums (single block)
__global__ void k_scan2() {
    __shared__ int s[512];
    int t = threadIdx.x;
    s[t] = (t < NBLK) ? g_bsum[t] : 0;
    __syncthreads();
    #pragma unroll
    for (int st = 1; st < 512; st <<= 1) {
        int v = (t >= st) ? s[t - st] : 0;
        __syncthreads();
        s[t] += v;
        __syncthreads();
    }
    if (t < NBLK) g_bpre[t] = (t == 0) ? 0 : s[t - 1];
    if (t == 0)   g_off[NN] = NE;
}

// final offsets + cursors + dis = rsqrt(deg)
__global__ void k_scan3() {
    __shared__ int s[256];
    int t = threadIdx.x;
    int i = blockIdx.x * 256 + t;
    int v = (i < NN) ? g_cnt[i] : 0;
    s[t] = v;
    __syncthreads();
    #pragma unroll
    for (int st = 1; st < 256; st <<= 1) {
        int u = (t >= st) ? s[t - st] : 0;
        __syncthreads();
        s[t] += u;
        __syncthreads();
    }
    if (i < NN) {
        int off = g_bpre[blockIdx.x] + s[t] - v;   // exclusive
        g_off[i] = off;
        g_cur[i] = off;
        float d = g_deg[i];
        g_dis[i] = d > 0.f ? rsqrtf(d) : 0.f;
    }
}

// fill CSR: rec[pos] = {row, norm}
__global__ void k_fill(const void* __restrict__ ei, const float* __restrict__ ew) {
    int e = blockIdx.x * 256 + threadIdx.x;
    if (e >= NE) return;
    int row = load_idx(ei, e);
    int col = load_idx(ei, NE + e);
    float norm = g_dis[row] * ew[e] * g_dis[col];
    int pos = atomicAdd(&g_cur[col], 1);
    unsigned long long r = (unsigned int)row |
                           ((unsigned long long)__float_as_uint(norm) << 32);
    g_rec[pos] = r;
}

// ---------------------------------------------------------------------------
// GEMM: h = X @ W.  2 rows/thread, 16 cols/thread, packed fma.rn.f32x2.
// W in shared as uint64 pairs; per-warp W reads are 4-way broadcast.
// ---------------------------------------------------------------------------
__device__ __forceinline__ unsigned long long ffma2(unsigned long long a,
                                                    unsigned long long b,
                                                    unsigned long long c) {
    unsigned long long d;
    asm("fma.rn.f32x2 %0, %1, %2, %3;" : "=l"(d) : "l"(a), "l"(b), "l"(c));
    return d;
}
__device__ __forceinline__ unsigned long long pack2(float lo) {
    unsigned long long d;
    asm("mov.b64 %0, {%1, %1};" : "=l"(d) : "f"(lo));
    return d;
}
__device__ __forceinline__ float2 unpack2(unsigned long long v) {
    float2 f;
    asm("mov.b64 {%0, %1}, %2;" : "=f"(f.x), "=f"(f.y) : "l"(v));
    return f;
}

__global__ void __launch_bounds__(256) k_gemm(const float* __restrict__ x,
                                              const float* __restrict__ W) {
    __shared__ unsigned long long Wsu[INC * OUTC / 2];   // 4096 x 8B = 32 KB
    int t = threadIdx.x;
    const unsigned long long* Wg = (const unsigned long long*)W;
    #pragma unroll
    for (int i = 0; i < 16; i++) Wsu[t + 256 * i] = Wg[t + 256 * i];
    __syncthreads();

    int cg = t & 3;                         // column group: cols cg*16 .. +15
    int r0 = blockIdx.x * 128 + (t >> 2) * 2;
    if (r0 >= NN) return;
    bool has1 = (r0 + 1) < NN;

    unsigned long long a0[8] = {0,0,0,0,0,0,0,0};
    unsigned long long a1[8] = {0,0,0,0,0,0,0,0};

    const float4* xr0 = (const float4*)(x + (long long)r0 * INC);
    const float4* xr1 = (const float4*)(x + (long long)(has1 ? r0 + 1 : r0) * INC);

    #pragma unroll 2
    for (int k4 = 0; k4 < 32; k4++) {
        float4 xv0 = __ldg(&xr0[k4]);
        float4 xv1 = __ldg(&xr1[k4]);
        float xs0[4] = {xv0.x, xv0.y, xv0.z, xv0.w};
        float xs1[4] = {xv1.x, xv1.y, xv1.z, xv1.w};
        #pragma unroll
        for (int kk = 0; kk < 4; kk++) {
            int k = k4 * 4 + kk;
            unsigned long long xx0 = pack2(xs0[kk]);
            unsigned long long xx1 = pack2(xs1[kk]);
            const unsigned long long* wrow = &Wsu[k * 32 + cg * 8];
            #pragma unroll
            for (int j = 0; j < 8; j++) {
                unsigned long long w = wrow[j];
                a0[j] = ffma2(xx0, w, a0[j]);
                a1[j] = ffma2(xx1, w, a1[j]);
            }
        }
    }

    float2* h2 = (float2*)g_h;
    long long base0 = (long long)r0 * 32 + cg * 8;
    #pragma unroll
    for (int j = 0; j < 8; j++) h2[base0 + j] = unpack2(a0[j]);
    if (has1) {
        long long base1 = base0 + 32;
        #pragma unroll
        for (int j = 0; j < 8; j++) h2[base1 + j] = unpack2(a1[j]);
    }
}

// ---------------------------------------------------------------------------
// gather: 16 threads per node, each owns one float4 of the 64 channels.
// acc starts at bias; sigmoid fused; single write, no atomics.
// ---------------------------------------------------------------------------
__global__ void k_gather(const float4* __restrict__ b4, float4* __restrict__ out) {
    int gid = blockIdx.x * 256 + threadIdx.x;    // exactly NN*16 threads
    int n = gid >> 4;
    if (n >= NN) return;
    int j = gid & 15;

    int p   = g_off[n];
    int end = g_off[n + 1];
    float4 acc = __ldg(&b4[j]);
    const float4* h4 = (const float4*)g_h;

    #pragma unroll 2
    for (; p < end; p++) {
        unsigned long long r = g_rec[p];         // broadcast across the 16 lanes
        int   row  = (int)(unsigned int)(r & 0xffffffffu);
        float norm = __uint_as_float((unsigned int)(r >> 32));
        float4 v = __ldg(&h4[row * 16 + j]);
        acc.x += norm * v.x;
        acc.y += norm * v.y;
        acc.z += norm * v.z;
        acc.w += norm * v.w;
    }
    acc.x = 1.f / (1.f + __expf(-acc.x));
    acc.y = 1.f / (1.f + __expf(-acc.y));
    acc.z = 1.f / (1.f + __expf(-acc.z));
    acc.w = 1.f / (1.f + __expf(-acc.w));
    out[gid] = acc;
}

// ---------------------------------------------------------------------------
extern "C" void kernel_launch(void* const* d_in, const int* in_sizes, int n_in,
                              void* d_out, int out_size) {
    const float* x  = (const float*)d_in[0];
    const void*  ei = d_in[1];
    const float* ew = (const float*)d_in[2];
    const float* W  = (const float*)d_in[3];
    const float* b  = (const float*)d_in[4];
    float* out = (float*)d_out;

    k_detect<<<1, 32>>>((const int*)ei);
    k_zero  <<<NBLK, 256>>>();
    k_count <<<(NE + 255) / 256, 256>>>(ei, ew);
    k_scan1 <<<NBLK, 256>>>();
    k_scan2 <<<1, 512>>>();
    k_scan3 <<<NBLK, 256>>>();
    k_gemm  <<<(NN + 127) / 128, 256>>>(x, W);
    k_fill  <<<(NE + 255) / 256, 256>>>(ei, ew);
    k_gather<<<NN * 16 / 256, 256>>>((const float4*)b, (float4*)out);
}

// round 9
// speedup vs baseline: 1.6381x; 1.6355x over previous
#include <cuda_runtime.h>
#include <cuda_fp16.h>

#define NN   100000
#define NE   1600000
#define INC  128
#define OUTC 64
#define NBLK 391                      // ceil(NN/256)

// ---- scratch (__device__ globals; no cudaMalloc allowed) -------------------
__device__ unsigned           g_h16[NN * OUTC / 2];  // h as half2, 12.8 MB
__device__ float              g_deg[NN];
__device__ float              g_dis[NN];
__device__ int                g_cnt[NN];
__device__ int                g_bsum[NBLK];
__device__ int                g_bpre[NBLK];
__device__ int                g_off[NN + 1];
__device__ int                g_cur[NN];
__device__ unsigned long long g_rec[NE];             // packed {row:int32, norm:f32}
__device__ int                g_is64;

// ---------------------------------------------------------------------------
// dtype detect (int64 indices < 100000 -> zero high words) + zero cnt/deg
// ---------------------------------------------------------------------------
__global__ void k_detect_zero(const int* __restrict__ ei32) {
    int i = blockIdx.x * 256 + threadIdx.x;
    if (i == 0) {
        int hi0 = ei32[1], hi1 = ei32[3], hi2 = ei32[5];
        g_is64 = (hi0 == 0 && hi1 == 0 && hi2 == 0) ? 1 : 0;
    }
    if (i < NN) { g_deg[i] = 0.f; g_cnt[i] = 0; }
}

__device__ __forceinline__ int load_idx(const void* ei, int pos) {
    if (g_is64) return (int)((const long long*)ei)[pos];
    return ((const int*)ei)[pos];
}

// count[col]++, deg[col] += w
__global__ void k_count(const void* __restrict__ ei, const float* __restrict__ ew) {
    int e = blockIdx.x * 256 + threadIdx.x;
    if (e >= NE) return;
    int col = load_idx(ei, NE + e);
    atomicAdd(&g_cnt[col], 1);
    atomicAdd(&g_deg[col], ew[e]);
}

// per-block sums of cnt
__global__ void k_scan1() {
    __shared__ int s[256];
    int t = threadIdx.x;
    int i = blockIdx.x * 256 + t;
    s[t] = (i < NN) ? g_cnt[i] : 0;
    __syncthreads();
    #pragma unroll
    for (int st = 128; st > 0; st >>= 1) {
        if (t < st) s[t] += s[t + st];
        __syncthreads();
    }
    if (t == 0) g_bsum[blockIdx.x] = s[0];
}

// exclusive scan of block sums (single block)
__global__ void k_scan2() {
    __shared__ int s[512];
    int t = threadIdx.x;
    s[t] = (t < NBLK) ? g_bsum[t] : 0;
    __syncthreads();
    #pragma unroll
    for (int st = 1; st < 512; st <<= 1) {
        int v = (t >= st) ? s[t - st] : 0;
        __syncthreads();
        s[t] += v;
        __syncthreads();
    }
    if (t < NBLK) g_bpre[t] = (t == 0) ? 0 : s[t - 1];
    if (t == 0)   g_off[NN] = NE;
}

// final offsets + cursors + dis = rsqrt(deg)
__global__ void k_scan3() {
    __shared__ int s[256];
    int t = threadIdx.x;
    int i = blockIdx.x * 256 + t;
    int v = (i < NN) ? g_cnt[i] : 0;
    s[t] = v;
    __syncthreads();
    #pragma unroll
    for (int st = 1; st < 256; st <<= 1) {
        int u = (t >= st) ? s[t - st] : 0;
        __syncthreads();
        s[t] += u;
        __syncthreads();
    }
    if (i < NN) {
        int off = g_bpre[blockIdx.x] + s[t] - v;   // exclusive
        g_off[i] = off;
        g_cur[i] = off;
        float d = g_deg[i];
        g_dis[i] = d > 0.f ? rsqrtf(d) : 0.f;
    }
}

// fill CSR: rec[pos] = {row, norm}
__global__ void k_fill(const void* __restrict__ ei, const float* __restrict__ ew) {
    int e = blockIdx.x * 256 + threadIdx.x;
    if (e >= NE) return;
    int row = load_idx(ei, e);
    int col = load_idx(ei, NE + e);
    float norm = g_dis[row] * ew[e] * g_dis[col];
    int pos = atomicAdd(&g_cur[col], 1);
    unsigned long long r = (unsigned int)row |
                           ((unsigned long long)__float_as_uint(norm) << 32);
    g_rec[pos] = r;
}

// ---------------------------------------------------------------------------
// GEMM: h = X @ W in fp32 (f32x2 FFMA), stored as half2.
// 2 rows/thread, 16 cols/thread. W in shared (32 KB, broadcast LDS).
// ---------------------------------------------------------------------------
__device__ __forceinline__ unsigned long long ffma2(unsigned long long a,
                                                    unsigned long long b,
                                                    unsigned long long c) {
    unsigned long long d;
    asm("fma.rn.f32x2 %0, %1, %2, %3;" : "=l"(d) : "l"(a), "l"(b), "l"(c));
    return d;
}
__device__ __forceinline__ unsigned long long pack2(float lo) {
    unsigned long long d;
    asm("mov.b64 %0, {%1, %1};" : "=l"(d) : "f"(lo));
    return d;
}
// pack accumulator (two fp32 lanes) -> one u32 holding half2 {lo, hi}
__device__ __forceinline__ unsigned tohalf2(unsigned long long v) {
    float lo, hi;
    asm("mov.b64 {%0, %1}, %2;" : "=f"(lo), "=f"(hi) : "l"(v));
    unsigned r;
    asm("cvt.rn.f16x2.f32 %0, %1, %2;" : "=r"(r) : "f"(hi), "f"(lo));
    return r;
}

__global__ void __launch_bounds__(256) k_gemm(const float* __restrict__ x,
                                              const float* __restrict__ W) {
    __shared__ unsigned long long Wsu[INC * OUTC / 2];   // 32 KB
    int t = threadIdx.x;
    const unsigned long long* Wg = (const unsigned long long*)W;
    #pragma unroll
    for (int i = 0; i < 16; i++) Wsu[t + 256 * i] = Wg[t + 256 * i];
    __syncthreads();

    int cg = t & 3;
    int r0 = blockIdx.x * 128 + (t >> 2) * 2;
    if (r0 >= NN) return;
    bool has1 = (r0 + 1) < NN;

    unsigned long long a0[8] = {0,0,0,0,0,0,0,0};
    unsigned long long a1[8] = {0,0,0,0,0,0,0,0};

    const float4* xr0 = (const float4*)(x + (long long)r0 * INC);
    const float4* xr1 = (const float4*)(x + (long long)(has1 ? r0 + 1 : r0) * INC);

    #pragma unroll 2
    for (int k4 = 0; k4 < 32; k4++) {
        float4 xv0 = __ldg(&xr0[k4]);
        float4 xv1 = __ldg(&xr1[k4]);
        float xs0[4] = {xv0.x, xv0.y, xv0.z, xv0.w};
        float xs1[4] = {xv1.x, xv1.y, xv1.z, xv1.w};
        #pragma unroll
        for (int kk = 0; kk < 4; kk++) {
            int k = k4 * 4 + kk;
            unsigned long long xx0 = pack2(xs0[kk]);
            unsigned long long xx1 = pack2(xs1[kk]);
            const unsigned long long* wrow = &Wsu[k * 32 + cg * 8];
            #pragma unroll
            for (int j = 0; j < 8; j++) {
                unsigned long long w = wrow[j];
                a0[j] = ffma2(xx0, w, a0[j]);
                a1[j] = ffma2(xx1, w, a1[j]);
            }
        }
    }

    // convert to half2 and store 16 B each (8 half2 = cols cg*16..+15)
    unsigned h0[8], h1[8];
    #pragma unroll
    for (int j = 0; j < 8; j++) {
        h0[j] = tohalf2(a0[j]);
        h1[j] = tohalf2(a1[j]);
    }
    uint4* hv = (uint4*)g_h16;                     // 8 uint4 per row
    long long base0 = (long long)r0 * 8 + cg * 2;
    hv[base0 + 0] = make_uint4(h0[0], h0[1], h0[2], h0[3]);
    hv[base0 + 1] = make_uint4(h0[4], h0[5], h0[6], h0[7]);
    if (has1) {
        hv[base0 + 8] = make_uint4(h1[0], h1[1], h1[2], h1[3]);
        hv[base0 + 9] = make_uint4(h1[4], h1[5], h1[6], h1[7]);
    }
}

// ---------------------------------------------------------------------------
// gather: 8 threads/node, each lane owns one uint4 (8 halves) of the h row —
// one coalesced 128 B line per edge. fp32 accumulate, sigmoid fused.
// ---------------------------------------------------------------------------
__device__ __forceinline__ void acc_line(float2* a, uint4 v, float norm) {
    float2 f0 = __half22float2(*(__half2*)&v.x);
    float2 f1 = __half22float2(*(__half2*)&v.y);
    float2 f2 = __half22float2(*(__half2*)&v.z);
    float2 f3 = __half22float2(*(__half2*)&v.w);
    a[0].x += norm * f0.x; a[0].y += norm * f0.y;
    a[1].x += norm * f1.x; a[1].y += norm * f1.y;
    a[2].x += norm * f2.x; a[2].y += norm * f2.y;
    a[3].x += norm * f3.x; a[3].y += norm * f3.y;
}

__global__ void __launch_bounds__(256) k_gather(const float4* __restrict__ b4,
                                                float4* __restrict__ out) {
    int gid = blockIdx.x * 256 + threadIdx.x;    // exactly NN*8 threads
    int n = gid >> 3;
    if (n >= NN) return;
    int j = gid & 7;                             // owns cols j*8 .. j*8+7

    int p   = g_off[n];
    int end = g_off[n + 1];

    float4 blo = __ldg(&b4[j * 2]);
    float4 bhi = __ldg(&b4[j * 2 + 1]);
    float2 acc[4] = {{blo.x, blo.y}, {blo.z, blo.w}, {bhi.x, bhi.y}, {bhi.z, bhi.w}};

    const uint4* h4 = (const uint4*)g_h16;

    // unrolled by 4 for MLP
    for (; p + 4 <= end; p += 4) {
        unsigned long long r0 = g_rec[p + 0];
        unsigned long long r1 = g_rec[p + 1];
        unsigned long long r2 = g_rec[p + 2];
        unsigned long long r3 = g_rec[p + 3];
        uint4 v0 = __ldg(&h4[(int)(unsigned)(r0 & 0xffffffffu) * 8 + j]);
        uint4 v1 = __ldg(&h4[(int)(unsigned)(r1 & 0xffffffffu) * 8 + j]);
        uint4 v2 = __ldg(&h4[(int)(unsigned)(r2 & 0xffffffffu) * 8 + j]);
        uint4 v3 = __ldg(&h4[(int)(unsigned)(r3 & 0xffffffffu) * 8 + j]);
        acc_line(acc, v0, __uint_as_float((unsigned)(r0 >> 32)));
        acc_line(acc, v1, __uint_as_float((unsigned)(r1 >> 32)));
        acc_line(acc, v2, __uint_as_float((unsigned)(r2 >> 32)));
        acc_line(acc, v3, __uint_as_float((unsigned)(r3 >> 32)));
    }
    for (; p < end; p++) {
        unsigned long long r = g_rec[p];
        uint4 v = __ldg(&h4[(int)(unsigned)(r & 0xffffffffu) * 8 + j]);
        acc_line(acc, v, __uint_as_float((unsigned)(r >> 32)));
    }

    float4 o0, o1;
    o0.x = 1.f / (1.f + __expf(-acc[0].x));
    o0.y = 1.f / (1.f + __expf(-acc[0].y));
    o0.z = 1.f / (1.f + __expf(-acc[1].x));
    o0.w = 1.f / (1.f + __expf(-acc[1].y));
    o1.x = 1.f / (1.f + __expf(-acc[2].x));
    o1.y = 1.f / (1.f + __expf(-acc[2].y));
    o1.z = 1.f / (1.f + __expf(-acc[3].x));
    o1.w = 1.f / (1.f + __expf(-acc[3].y));
    out[n * 16 + j * 2]     = o0;
    out[n * 16 + j * 2 + 1] = o1;
}

// ---------------------------------------------------------------------------
extern "C" void kernel_launch(void* const* d_in, const int* in_sizes, int n_in,
                              void* d_out, int out_size) {
    const float* x  = (const float*)d_in[0];
    const void*  ei = d_in[1];
    const float* ew = (const float*)d_in[2];
    const float* W  = (const float*)d_in[3];
    const float* b  = (const float*)d_in[4];
    float* out = (float*)d_out;

    k_detect_zero<<<NBLK, 256>>>((const int*)ei);
    k_count <<<(NE + 255) / 256, 256>>>(ei, ew);
    k_scan1 <<<NBLK, 256>>>();
    k_scan2 <<<1, 512>>>();
    k_scan3 <<<NBLK, 256>>>();
    k_gemm  <<<(NN + 127) / 128, 256>>>(x, W);
    k_fill  <<<(NE + 255) / 256, 256>>>(ei, ew);
    k_gather<<<NN * 8 / 256, 256>>>((const float4*)b, (float4*)out);
}